// round 9
// baseline (speedup 1.0000x reference)
#include <cuda_runtime.h>
#include <cuda_fp16.h>
#include <math.h>
#include <stdint.h>

// ---------------------------------------------------------------------------
// attention_83932250898666 : B=4, N=2048, D=1024
// d_out layout (float32):
//   [0, 16777216)        out   = concat(x, LN(x+att))   [B,N,2D]
//   [16777216, 25165824) att_score                      [B,N,D]
//   [25165824, 41943040) weight = softmax(QK^T/32)      [B,N,N]
// GEMMs: single-pass fp16 mma.sync (HMMA), fp32 accumulate.
// Round 9: 512-thread CTA, block 128x256, warp 32x64 (4m x 4n), 16 warps/SM;
//          V^T produced directly by GEMM (bias-per-row epilogue).
// ---------------------------------------------------------------------------

#define Bb 4
#define Nn 2048
#define Dd 1024
#define MT (Bb*Nn)   // 8192

// ------------------------- device scratch (no allocs) ----------------------
__device__ __half g_x16[(size_t)MT * Dd];
__device__ __half g_W16[(size_t)3 * Dd * Dd];      // [z][n][k] transposed weights
__device__ float  g_b[2 * Dd];                     // biases q,k
__device__ __half g_QKV[(size_t)2 * MT * Dd];      // Q | K
__device__ __half g_Vt[(size_t)MT * Dd];           // per-batch V^T [b][d][n]
__device__ __half g_w16[(size_t)Bb * Nn * Nn];     // softmax weights fp16

// ------------------------------ PTX helpers --------------------------------
__device__ __forceinline__ uint32_t smem_u32(const void* p) {
    uint32_t a;
    asm("{ .reg .u64 t; cvta.to.shared.u64 t, %1; cvt.u32.u64 %0, t; }" : "=r"(a) : "l"(p));
    return a;
}

#define CP16(dst, src) \
    asm volatile("cp.async.cg.shared.global [%0], [%1], 16;" :: "r"(dst), "l"(src))
#define CP_COMMIT() asm volatile("cp.async.commit_group;" ::: "memory")
#define CP_WAIT1()  asm volatile("cp.async.wait_group 1;" ::: "memory")

#define LDSM4(R0, R1, R2, R3, A) \
    asm volatile("ldmatrix.sync.aligned.m8n8.x4.shared.b16 {%0,%1,%2,%3}, [%4];" \
                 : "=r"(R0), "=r"(R1), "=r"(R2), "=r"(R3) : "r"(A))

#define MMAH(D, A0, A1, A2, A3, B0, B1) \
    asm volatile("mma.sync.aligned.m16n8k16.row.col.f32.f16.f16.f32 " \
                 "{%0,%1,%2,%3},{%4,%5,%6,%7},{%8,%9},{%0,%1,%2,%3};" \
                 : "+f"((D)[0]), "+f"((D)[1]), "+f"((D)[2]), "+f"((D)[3]) \
                 : "r"(A0), "r"(A1), "r"(A2), "r"(A3), "r"(B0), "r"(B1))

// ------------------------------- MMA GEMM ----------------------------------
// C[M,N] = alpha*(A @ Bmat^T)(+bias). A:[M,K] fp16 (ld=K), Bmat:[N,K] fp16 (ld=K).
// Block 128x256, 16 warps (4m x 4n), warp tile 32x64, K-chunk 64, 3-stage cp.async.
#define NTHR 512
#define BMm 128
#define BNm 256
#define BKm 64
#define LDSm 72                          // padded row length in halves (144B)
#define OPA (128 * LDSm * 2)             // 18432 B
#define OPBB (256 * LDSm * 2)            // 36864 B
#define STGB (OPA + OPBB)                // 55296 B
#define NSTAGE 3
#define SMEM_BYTES (NSTAGE * STGB)       // 165888

// EPI: 0 fp32 out, 1 fp16 out.  BIASMODE: 0 none, 1 per-col, 2 per-row.
template<int EPI, int BIASMODE>
__global__ __launch_bounds__(NTHR, 1)
void mma_gemm(const __half* __restrict__ A, const __half* __restrict__ B,
              const float* __restrict__ bias,
              float* __restrict__ Cf, __half* __restrict__ Ch,
              int K, int ldc,
              long long sA, long long sB, long long sC, long long sBias, float alpha)
{
    extern __shared__ char smem[];
    const uint32_t sbase = smem_u32(smem);
    const int tid  = threadIdx.x;
    const int wid  = tid >> 5;
    const int lane = tid & 31;
    const int wy = wid >> 2;            // 0..3  (m, 32 rows each)
    const int wx = wid & 3;             // 0..3  (n, 64 cols each)
    const int m0 = blockIdx.y * BMm;
    const int n0 = blockIdx.x * BNm;
    A += (long long)blockIdx.z * sA;
    B += (long long)blockIdx.z * sB;
    if (BIASMODE) bias += (long long)blockIdx.z * sBias;

    float acc[2][8][4];
#pragma unroll
    for (int i = 0; i < 2; i++)
#pragma unroll
        for (int j = 0; j < 8; j++)
#pragma unroll
            for (int q = 0; q < 4; q++) acc[i][j][q] = 0.0f;

    const int nch = K / BKm;

    // full-stage load (prologue): A 1024 chunks (2/thr), B 2048 chunks (4/thr)
    auto load_stage = [&](int s, int k0) {
        uint32_t sb = sbase + s * STGB;
#pragma unroll
        for (int t = 0; t < 2; t++) {
            int idx = tid + NTHR * t;
            int r = idx >> 3, c = idx & 7;
            CP16(sb + (uint32_t)(r * LDSm + c * 8) * 2,
                 A + (long long)(m0 + r) * K + k0 + c * 8);
        }
#pragma unroll
        for (int t = 0; t < 4; t++) {
            int idx = tid + NTHR * t;
            int r = idx >> 3, c = idx & 7;
            CP16(sb + OPA + (uint32_t)(r * LDSm + c * 8) * 2,
                 B + (long long)(n0 + r) * K + k0 + c * 8);
        }
    };

    // spread load: 6 parts over 8 slots (p in [0,8))
    auto load_part = [&](int s, int k0, int p) {
        uint32_t sb = sbase + s * STGB;
        if (p < 2) {
            int idx = tid + NTHR * p;
            int r = idx >> 3, c = idx & 7;
            CP16(sb + (uint32_t)(r * LDSm + c * 8) * 2,
                 A + (long long)(m0 + r) * K + k0 + c * 8);
        } else if (p < 6) {
            int idx = tid + NTHR * (p - 2);
            int r = idx >> 3, c = idx & 7;
            CP16(sb + OPA + (uint32_t)(r * LDSm + c * 8) * 2,
                 B + (long long)(n0 + r) * K + k0 + c * 8);
        }
    };

    load_stage(0, 0);       CP_COMMIT();
    load_stage(1, BKm);     CP_COMMIT();

    // ldmatrix lane address components
    const int arow = (lane & 7) + ((lane >> 3) & 1) * 8;   // 0..15
    const int acol = (lane >> 4) * 8;                      // 0 / 8
    const int brow = (lane & 7) + (lane >> 4) * 8;
    const int bcol = ((lane >> 3) & 1) * 8;

    uint32_t af[2][2][4];      // A fragments, double buffered over ks
    uint32_t bf[2][4][2];      // B fragments, rolling buffer per half-ks (4 j each)

    auto ldA = [&](int buf, uint32_t sb, int ks) {
#pragma unroll
        for (int i = 0; i < 2; i++) {
            uint32_t aoff = (uint32_t)((32 * wy + 16 * i + arow) * LDSm
                                       + ks * 16 + acol) * 2;
            LDSM4(af[buf][i][0], af[buf][i][1], af[buf][i][2], af[buf][i][3], sb + aoff);
        }
    };
    // loads 4 j-tiles (half the warp's 8) for a given (ks, jh)
    auto ldB = [&](int buf, uint32_t sb, int ks, int jh) {
#pragma unroll
        for (int jpp = 0; jpp < 2; jpp++) {
            uint32_t boff = (uint32_t)((64 * wx + 16 * (2 * jh + jpp) + brow) * LDSm
                                       + ks * 16 + bcol) * 2;
            LDSM4(bf[buf][2*jpp][0], bf[buf][2*jpp][1], bf[buf][2*jpp+1][0], bf[buf][2*jpp+1][1],
                  sb + OPA + boff);
        }
    };

    for (int c = 0; c < nch; c++) {
        CP_WAIT1();
        __syncthreads();
        const uint32_t sb = sbase + (c % NSTAGE) * STGB;
        const bool pf = (c + 2 < nch);
        const int s2 = (c + 2) % NSTAGE;
        const int k2 = (c + 2) * BKm;

        ldA(0, sb, 0);
        ldB(0, sb, 0, 0);
#pragma unroll
        for (int idx = 0; idx < 8; idx++) {          // ks = idx>>1, jh = idx&1
            const int ks = idx >> 1, jh = idx & 1;
            if (idx < 7) ldB((idx + 1) & 1, sb, (idx + 1) >> 1, (idx + 1) & 1);
            if (jh == 0 && ks < 3) ldA((ks + 1) & 1, sb, ks + 1);
            if (pf) load_part(s2, k2, idx);
            const int ab = ks & 1, bb = idx & 1;
#pragma unroll
            for (int i = 0; i < 2; i++)
#pragma unroll
                for (int jj = 0; jj < 4; jj++)
                    MMAH(acc[i][jh * 4 + jj],
                         af[ab][i][0], af[ab][i][1], af[ab][i][2], af[ab][i][3],
                         bf[bb][jj][0], bf[bb][jj][1]);
        }
        CP_COMMIT();
    }

    // ------------------------------ epilogue --------------------------------
    const int g  = lane >> 2;
    const int t4 = lane & 3;
    const long long cb = (long long)blockIdx.z * sC;
#pragma unroll
    for (int i = 0; i < 2; i++) {
#pragma unroll
        for (int j = 0; j < 8; j++) {
            int mrow = m0 + 32 * wy + 16 * i + g;
            int ncol = n0 + 64 * wx + 8 * j + 2 * t4;
            float v00 = acc[i][j][0] * alpha, v01 = acc[i][j][1] * alpha;
            float v10 = acc[i][j][2] * alpha, v11 = acc[i][j][3] * alpha;
            long long o0 = cb + (long long)mrow * ldc + ncol;
            long long o1 = cb + (long long)(mrow + 8) * ldc + ncol;
            if (BIASMODE == 1) {
                float b0 = bias[ncol], b1 = bias[ncol + 1];
                v00 += b0; v01 += b1; v10 += b0; v11 += b1;
            } else if (BIASMODE == 2) {
                float br0 = bias[mrow], br1 = bias[mrow + 8];
                v00 += br0; v01 += br0; v10 += br1; v11 += br1;
            }
            if (EPI == 0) {
                *(float2*)(Cf + o0) = make_float2(v00, v01);
                *(float2*)(Cf + o1) = make_float2(v10, v11);
            } else {
                *(__half2*)(Ch + o0) = __floats2half2_rn(v00, v01);
                *(__half2*)(Ch + o1) = __floats2half2_rn(v10, v11);
            }
        }
    }
}

// --------------------------- aux kernels ------------------------------------
// fp32 -> fp16, 4 elts/thread
__global__ void cvt_x(const float* __restrict__ in, __half* __restrict__ out)
{
    long long i = ((long long)blockIdx.x * blockDim.x + threadIdx.x) * 4;
    float4 v = *(const float4*)(in + i);
    *(__half2*)(out + i)     = __floats2half2_rn(v.x, v.y);
    *(__half2*)(out + i + 2) = __floats2half2_rn(v.z, v.w);
}

__global__ void copy_bias(const float* __restrict__ b0, const float* __restrict__ b1,
                          float* __restrict__ dst)
{
    int z = blockIdx.x;
    const float* s = (z == 0) ? b0 : b1;
    dst[z * Dd + threadIdx.x] = s[threadIdx.x];
}

// Wt[n,k] = W[k,n] fp16 ; z selects which W
__global__ void transW(const float* __restrict__ W0, const float* __restrict__ W1,
                       const float* __restrict__ W2, __half* __restrict__ out)
{
    __shared__ float t[32][33];
    const float* W = (blockIdx.z == 0) ? W0 : (blockIdx.z == 1) ? W1 : W2;
    __half* o = out + (size_t)blockIdx.z * Dd * Dd;
    int bx = blockIdx.x * 32, by = blockIdx.y * 32;
    int tx = threadIdx.x, ty = threadIdx.y;
#pragma unroll
    for (int r = 0; r < 4; r++)
        t[ty + 8 * r][tx] = W[(long long)(by + ty + 8 * r) * Dd + bx + tx];
    __syncthreads();
#pragma unroll
    for (int r = 0; r < 4; r++)
        o[(long long)(bx + ty + 8 * r) * Dd + by + tx] = __float2half_rn(t[tx][ty + 8 * r]);
}

// single-read row softmax: values held in registers; writes fp32 + fp16
__global__ void softmax_split(float* __restrict__ W, __half* __restrict__ wh)
{
    long long row = blockIdx.x;
    float* p = W + row * (long long)Nn;
    __half* ph = wh + row * (long long)Nn;
    __shared__ float red[8];
    const int tid = threadIdx.x;
    const int lane = tid & 31, warp = tid >> 5;

    float e[8];
    {
        float4 v0 = *(const float4*)(p + tid * 8);
        float4 v1 = *(const float4*)(p + tid * 8 + 4);
        e[0]=v0.x; e[1]=v0.y; e[2]=v0.z; e[3]=v0.w;
        e[4]=v1.x; e[5]=v1.y; e[6]=v1.z; e[7]=v1.w;
    }
    float mx = e[0];
#pragma unroll
    for (int i = 1; i < 8; i++) mx = fmaxf(mx, e[i]);
#pragma unroll
    for (int s = 16; s > 0; s >>= 1)
        mx = fmaxf(mx, __shfl_xor_sync(0xffffffffu, mx, s));
    if (lane == 0) red[warp] = mx;
    __syncthreads();
    mx = red[0];
#pragma unroll
    for (int w = 1; w < 8; w++) mx = fmaxf(mx, red[w]);
    __syncthreads();

    float sum = 0.0f;
#pragma unroll
    for (int i = 0; i < 8; i++) { e[i] = expf(e[i] - mx); sum += e[i]; }
#pragma unroll
    for (int s = 16; s > 0; s >>= 1)
        sum += __shfl_xor_sync(0xffffffffu, sum, s);
    if (lane == 0) red[warp] = sum;
    __syncthreads();
    sum = red[0];
#pragma unroll
    for (int w = 1; w < 8; w++) sum += red[w];
    float inv = 1.0f / sum;

    float4 o0, o1;
    o0.x = e[0]*inv; o0.y = e[1]*inv; o0.z = e[2]*inv; o0.w = e[3]*inv;
    o1.x = e[4]*inv; o1.y = e[5]*inv; o1.z = e[6]*inv; o1.w = e[7]*inv;
    *(float4*)(p + tid * 8)     = o0;
    *(float4*)(p + tid * 8 + 4) = o1;
    *(__half2*)(ph + tid * 8)     = __floats2half2_rn(o0.x, o0.y);
    *(__half2*)(ph + tid * 8 + 2) = __floats2half2_rn(o0.z, o0.w);
    *(__half2*)(ph + tid * 8 + 4) = __floats2half2_rn(o1.x, o1.y);
    *(__half2*)(ph + tid * 8 + 6) = __floats2half2_rn(o1.z, o1.w);
}

// residual + layernorm + concat(x, ln)
__global__ void ln_concat(const float* __restrict__ x, const float* __restrict__ att,
                          const float* __restrict__ gamma, const float* __restrict__ beta,
                          float* __restrict__ out)
{
    long long row = blockIdx.x;
    const float* xr = x + row * Dd;
    const float* ar = att + row * Dd;
    float* o = out + row * (2 * Dd);
    __shared__ float red[256];
    int tid = threadIdx.x;

    float h[4], s = 0.0f;
#pragma unroll
    for (int i = 0; i < 4; i++) { int c = tid + i * 256; h[i] = xr[c] + ar[c]; s += h[i]; }
    red[tid] = s; __syncthreads();
#pragma unroll
    for (int st = 128; st > 0; st >>= 1) {
        if (tid < st) red[tid] += red[tid + st];
        __syncthreads();
    }
    float mu = red[0] * (1.0f / Dd); __syncthreads();

    float v = 0.0f;
#pragma unroll
    for (int i = 0; i < 4; i++) { float d = h[i] - mu; v += d * d; }
    red[tid] = v; __syncthreads();
#pragma unroll
    for (int st = 128; st > 0; st >>= 1) {
        if (tid < st) red[tid] += red[tid + st];
        __syncthreads();
    }
    float rstd = rsqrtf(red[0] * (1.0f / Dd) + 1e-5f);
#pragma unroll
    for (int i = 0; i < 4; i++) {
        int c = tid + i * 256;
        o[c]      = xr[c];
        o[Dd + c] = (h[i] - mu) * rstd * gamma[c] + beta[c];
    }
}

// ------------------------------- launcher -----------------------------------
extern "C" void kernel_launch(void* const* d_in, const int* in_sizes, int n_in,
                              void* d_out, int out_size)
{
    const float* x     = (const float*)d_in[0];
    const float* Wk    = (const float*)d_in[1];
    const float* bk    = (const float*)d_in[2];
    const float* Wq    = (const float*)d_in[3];
    const float* bq    = (const float*)d_in[4];
    const float* Wv    = (const float*)d_in[5];
    const float* bv    = (const float*)d_in[6];
    const float* gamma = (const float*)d_in[7];
    const float* beta  = (const float*)d_in[8];

    float* out = (float*)d_out;
    float* att = out + (long long)MT * 2 * Dd;
    float* wgt = att + (long long)MT * Dd;

    __half *x16, *W16, *QKV, *Vt, *w16;
    float* bqk;
    cudaGetSymbolAddress((void**)&x16, g_x16);
    cudaGetSymbolAddress((void**)&W16, g_W16);
    cudaGetSymbolAddress((void**)&bqk, g_b);
    cudaGetSymbolAddress((void**)&QKV, g_QKV);
    cudaGetSymbolAddress((void**)&Vt,  g_Vt);
    cudaGetSymbolAddress((void**)&w16, g_w16);

    cudaFuncSetAttribute(mma_gemm<0, 0>, cudaFuncAttributeMaxDynamicSharedMemorySize, SMEM_BYTES);
    cudaFuncSetAttribute(mma_gemm<1, 1>, cudaFuncAttributeMaxDynamicSharedMemorySize, SMEM_BYTES);
    cudaFuncSetAttribute(mma_gemm<1, 2>, cudaFuncAttributeMaxDynamicSharedMemorySize, SMEM_BYTES);

    // 1) precision conversions
    cvt_x<<<MT * Dd / 4096, 1024>>>(x, x16);
    copy_bias<<<2, Dd>>>(bq, bk, bqk);
    {
        dim3 g(Dd / 32, Dd / 32, 3), b(32, 8);
        transW<<<g, b>>>(Wq, Wk, Wv, W16);
    }

    // 2) fused Q,K projection: z in {Q,K}
    {
        dim3 g(Dd / BNm, MT / BMm, 2), b(NTHR);
        mma_gemm<1, 1><<<g, b, SMEM_BYTES>>>(x16, W16, bqk, nullptr, QKV,
                                             Dd, Dd,
                                             0, (long long)Dd * Dd, (long long)MT * Dd,
                                             Dd, 1.0f);
    }

    // 3) Vt[b][d,n] = Wv^T @ x_b^T + bv (bias per row) -> fp16, per batch
    {
        dim3 g(Nn / BNm, Dd / BMm, Bb), b(NTHR);
        mma_gemm<1, 2><<<g, b, SMEM_BYTES>>>(W16 + (size_t)2 * Dd * Dd, x16, bv,
                                             nullptr, Vt,
                                             Dd, Nn,
                                             0, (long long)Nn * Dd, (long long)Dd * Nn,
                                             0, 1.0f);
    }

    // 4) scores = Q @ K^T / 32 -> wgt (fp32)
    {
        dim3 g(Nn / BNm, Nn / BMm, Bb), b(NTHR);
        mma_gemm<0, 0><<<g, b, SMEM_BYTES>>>(QKV, QKV + (size_t)MT * Dd, nullptr,
                                             wgt, nullptr,
                                             Dd, Nn,
                                             (long long)Nn * Dd, (long long)Nn * Dd,
                                             (long long)Nn * Nn, 0, 1.0f / 32.0f);
    }

    // 5) softmax rows in place + fp16 copy (single gmem read)
    softmax_split<<<Bb * Nn, 256>>>(wgt, w16);

    // 6) att = weight @ V -> att (fp32)
    {
        dim3 g(Dd / BNm, Nn / BMm, Bb), b(NTHR);
        mma_gemm<0, 0><<<g, b, SMEM_BYTES>>>(w16, Vt, nullptr, att, nullptr,
                                             Nn, Dd,
                                             (long long)Nn * Nn, (long long)Nn * Dd,
                                             (long long)Nn * Dd, 0, 1.0f);
    }

    // 7) out = concat(x, LN(x + att))
    ln_concat<<<Bb * Nn, 256>>>(x, att, gamma, beta, out);
}

// round 10
// speedup vs baseline: 1.0642x; 1.0642x over previous
#include <cuda_runtime.h>
#include <cuda_fp16.h>
#include <math.h>
#include <stdint.h>

// ---------------------------------------------------------------------------
// attention_83932250898666 : B=4, N=2048, D=1024
// d_out layout (float32):
//   [0, 16777216)        out   = concat(x, LN(x+att))   [B,N,2D]
//   [16777216, 25165824) att_score                      [B,N,D]
//   [25165824, 41943040) weight = softmax(QK^T/32)      [B,N,N]
// GEMMs: single-pass fp16 mma.sync (HMMA), fp32 accumulate.
// Round 10: round-7 GEMM config (128x128 blk, 32x64 warp, 2 CTA/SM, rolling
//           pipeline) + round-9 aux (Vt via GEMM, single-read softmax).
// ---------------------------------------------------------------------------

#define Bb 4
#define Nn 2048
#define Dd 1024
#define MT (Bb*Nn)   // 8192

// ------------------------- device scratch (no allocs) ----------------------
__device__ __half g_x16[(size_t)MT * Dd];
__device__ __half g_W16[(size_t)3 * Dd * Dd];      // [z][n][k] transposed weights
__device__ float  g_b[2 * Dd];                     // biases q,k
__device__ __half g_QK[(size_t)2 * MT * Dd];       // Q | K
__device__ __half g_Vt[(size_t)MT * Dd];           // per-batch V^T [b][d][n]
__device__ __half g_w16[(size_t)Bb * Nn * Nn];     // softmax weights fp16

// ------------------------------ PTX helpers --------------------------------
__device__ __forceinline__ uint32_t smem_u32(const void* p) {
    uint32_t a;
    asm("{ .reg .u64 t; cvta.to.shared.u64 t, %1; cvt.u32.u64 %0, t; }" : "=r"(a) : "l"(p));
    return a;
}

#define CP16(dst, src) \
    asm volatile("cp.async.cg.shared.global [%0], [%1], 16;" :: "r"(dst), "l"(src))
#define CP_COMMIT() asm volatile("cp.async.commit_group;" ::: "memory")
#define CP_WAIT1()  asm volatile("cp.async.wait_group 1;" ::: "memory")

#define LDSM4(R0, R1, R2, R3, A) \
    asm volatile("ldmatrix.sync.aligned.m8n8.x4.shared.b16 {%0,%1,%2,%3}, [%4];" \
                 : "=r"(R0), "=r"(R1), "=r"(R2), "=r"(R3) : "r"(A))

#define MMAH(D, A0, A1, A2, A3, B0, B1) \
    asm volatile("mma.sync.aligned.m16n8k16.row.col.f32.f16.f16.f32 " \
                 "{%0,%1,%2,%3},{%4,%5,%6,%7},{%8,%9},{%0,%1,%2,%3};" \
                 : "+f"((D)[0]), "+f"((D)[1]), "+f"((D)[2]), "+f"((D)[3]) \
                 : "r"(A0), "r"(A1), "r"(A2), "r"(A3), "r"(B0), "r"(B1))

// ------------------------------- MMA GEMM ----------------------------------
// C[M,N] = alpha*(A @ Bmat^T)(+bias). A:[M,K] fp16 (ld=K), Bmat:[N,K] fp16 (ld=K).
// Block 128x128, 8 warps (4m x 2n), warp tile 32x64, K-chunk 64, 3-stage cp.async.
#define BMm 128
#define BNm 128
#define BKm 64
#define LDSm 72                          // padded row length in halves (144B)
#define OPA (128 * LDSm * 2)             // 18432 B
#define STGB (2 * OPA)                   // 36864 B
#define NSTAGE 3
#define SMEM_BYTES (NSTAGE * STGB)       // 110592

// EPI: 0 fp32 out, 1 fp16 out.  BIASMODE: 0 none, 1 per-col, 2 per-row.
template<int EPI, int BIASMODE>
__global__ __launch_bounds__(256, 2)
void mma_gemm(const __half* __restrict__ A, const __half* __restrict__ B,
              const float* __restrict__ bias,
              float* __restrict__ Cf, __half* __restrict__ Ch,
              int K, int ldc,
              long long sA, long long sB, long long sC, long long sBias, float alpha)
{
    extern __shared__ char smem[];
    const uint32_t sbase = smem_u32(smem);
    const int tid  = threadIdx.x;
    const int wid  = tid >> 5;
    const int lane = tid & 31;
    const int wy = wid >> 1;            // 0..3  (m, 32 rows each)
    const int wx = wid & 1;             // 0..1  (n, 64 cols each)
    const int m0 = blockIdx.y * BMm;
    const int n0 = blockIdx.x * BNm;
    A += (long long)blockIdx.z * sA;
    B += (long long)blockIdx.z * sB;
    if (BIASMODE) bias += (long long)blockIdx.z * sBias;

    float acc[2][8][4];
#pragma unroll
    for (int i = 0; i < 2; i++)
#pragma unroll
        for (int j = 0; j < 8; j++)
#pragma unroll
            for (int q = 0; q < 4; q++) acc[i][j][q] = 0.0f;

    const int nch = K / BKm;

    // full-stage load (prologue only)
    auto load_stage = [&](int s, int k0) {
        uint32_t sb = sbase + s * STGB;
#pragma unroll
        for (int t = 0; t < 4; t++) {
            int idx = tid + 256 * t;
            int r = idx >> 3, c = idx & 7;
            CP16(sb + (uint32_t)(r * LDSm + c * 8) * 2,
                 A + (long long)(m0 + r) * K + k0 + c * 8);
        }
#pragma unroll
        for (int t = 0; t < 4; t++) {
            int idx = tid + 256 * t;
            int r = idx >> 3, c = idx & 7;
            CP16(sb + OPA + (uint32_t)(r * LDSm + c * 8) * 2,
                 B + (long long)(n0 + r) * K + k0 + c * 8);
        }
    };

    // 1/8th of a stage load (spread across mainloop slots); p in [0,8)
    auto load_part = [&](int s, int k0, int p) {
        uint32_t sb = sbase + s * STGB;
        if (p < 4) {
            int idx = tid + 256 * p;
            int r = idx >> 3, c = idx & 7;
            CP16(sb + (uint32_t)(r * LDSm + c * 8) * 2,
                 A + (long long)(m0 + r) * K + k0 + c * 8);
        } else {
            int idx = tid + 256 * (p - 4);
            int r = idx >> 3, c = idx & 7;
            CP16(sb + OPA + (uint32_t)(r * LDSm + c * 8) * 2,
                 B + (long long)(n0 + r) * K + k0 + c * 8);
        }
    };

    load_stage(0, 0);       CP_COMMIT();
    load_stage(1, BKm);     CP_COMMIT();

    // ldmatrix lane address components
    const int arow = (lane & 7) + ((lane >> 3) & 1) * 8;   // 0..15
    const int acol = (lane >> 4) * 8;                      // 0 / 8
    const int brow = (lane & 7) + (lane >> 4) * 8;
    const int bcol = ((lane >> 3) & 1) * 8;

    uint32_t af[2][2][4];      // A fragments, double buffered over ks
    uint32_t bf[2][4][2];      // B fragments, rolling buffer per half-ks (4 j each)

    auto ldA = [&](int buf, uint32_t sb, int ks) {
#pragma unroll
        for (int i = 0; i < 2; i++) {
            uint32_t aoff = (uint32_t)((32 * wy + 16 * i + arow) * LDSm
                                       + ks * 16 + acol) * 2;
            LDSM4(af[buf][i][0], af[buf][i][1], af[buf][i][2], af[buf][i][3], sb + aoff);
        }
    };
    // loads 4 j-tiles (half the warp's 8) for a given (ks, jh)
    auto ldB = [&](int buf, uint32_t sb, int ks, int jh) {
#pragma unroll
        for (int jpp = 0; jpp < 2; jpp++) {
            uint32_t boff = (uint32_t)((64 * wx + 16 * (2 * jh + jpp) + brow) * LDSm
                                       + ks * 16 + bcol) * 2;
            LDSM4(bf[buf][2*jpp][0], bf[buf][2*jpp][1], bf[buf][2*jpp+1][0], bf[buf][2*jpp+1][1],
                  sb + OPA + boff);
        }
    };

    for (int c = 0; c < nch; c++) {
        CP_WAIT1();
        __syncthreads();
        const uint32_t sb = sbase + (c % NSTAGE) * STGB;
        const bool pf = (c + 2 < nch);
        const int s2 = (c + 2) % NSTAGE;
        const int k2 = (c + 2) * BKm;

        ldA(0, sb, 0);
        ldB(0, sb, 0, 0);
#pragma unroll
        for (int idx = 0; idx < 8; idx++) {          // ks = idx>>1, jh = idx&1
            const int ks = idx >> 1, jh = idx & 1;
            if (idx < 7) ldB((idx + 1) & 1, sb, (idx + 1) >> 1, (idx + 1) & 1);
            if (jh == 0 && ks < 3) ldA((ks + 1) & 1, sb, ks + 1);
            if (pf) load_part(s2, k2, idx);
            const int ab = ks & 1, bb = idx & 1;
#pragma unroll
            for (int i = 0; i < 2; i++)
#pragma unroll
                for (int jj = 0; jj < 4; jj++)
                    MMAH(acc[i][jh * 4 + jj],
                         af[ab][i][0], af[ab][i][1], af[ab][i][2], af[ab][i][3],
                         bf[bb][jj][0], bf[bb][jj][1]);
        }
        CP_COMMIT();
    }

    // ------------------------------ epilogue --------------------------------
    const int g  = lane >> 2;
    const int t4 = lane & 3;
    const long long cb = (long long)blockIdx.z * sC;
#pragma unroll
    for (int i = 0; i < 2; i++) {
#pragma unroll
        for (int j = 0; j < 8; j++) {
            int mrow = m0 + 32 * wy + 16 * i + g;
            int ncol = n0 + 64 * wx + 8 * j + 2 * t4;
            float v00 = acc[i][j][0] * alpha, v01 = acc[i][j][1] * alpha;
            float v10 = acc[i][j][2] * alpha, v11 = acc[i][j][3] * alpha;
            long long o0 = cb + (long long)mrow * ldc + ncol;
            long long o1 = cb + (long long)(mrow + 8) * ldc + ncol;
            if (BIASMODE == 1) {
                float b0 = bias[ncol], b1 = bias[ncol + 1];
                v00 += b0; v01 += b1; v10 += b0; v11 += b1;
            } else if (BIASMODE == 2) {
                float br0 = bias[mrow], br1 = bias[mrow + 8];
                v00 += br0; v01 += br0; v10 += br1; v11 += br1;
            }
            if (EPI == 0) {
                *(float2*)(Cf + o0) = make_float2(v00, v01);
                *(float2*)(Cf + o1) = make_float2(v10, v11);
            } else {
                *(__half2*)(Ch + o0) = __floats2half2_rn(v00, v01);
                *(__half2*)(Ch + o1) = __floats2half2_rn(v10, v11);
            }
        }
    }
}

// --------------------------- aux kernels ------------------------------------
// fp32 -> fp16, 4 elts/thread
__global__ void cvt_x(const float* __restrict__ in, __half* __restrict__ out)
{
    long long i = ((long long)blockIdx.x * blockDim.x + threadIdx.x) * 4;
    float4 v = *(const float4*)(in + i);
    *(__half2*)(out + i)     = __floats2half2_rn(v.x, v.y);
    *(__half2*)(out + i + 2) = __floats2half2_rn(v.z, v.w);
}

__global__ void copy_bias(const float* __restrict__ b0, const float* __restrict__ b1,
                          float* __restrict__ dst)
{
    int z = blockIdx.x;
    const float* s = (z == 0) ? b0 : b1;
    dst[z * Dd + threadIdx.x] = s[threadIdx.x];
}

// Wt[n,k] = W[k,n] fp16 ; z selects which W
__global__ void transW(const float* __restrict__ W0, const float* __restrict__ W1,
                       const float* __restrict__ W2, __half* __restrict__ out)
{
    __shared__ float t[32][33];
    const float* W = (blockIdx.z == 0) ? W0 : (blockIdx.z == 1) ? W1 : W2;
    __half* o = out + (size_t)blockIdx.z * Dd * Dd;
    int bx = blockIdx.x * 32, by = blockIdx.y * 32;
    int tx = threadIdx.x, ty = threadIdx.y;
#pragma unroll
    for (int r = 0; r < 4; r++)
        t[ty + 8 * r][tx] = W[(long long)(by + ty + 8 * r) * Dd + bx + tx];
    __syncthreads();
#pragma unroll
    for (int r = 0; r < 4; r++)
        o[(long long)(bx + ty + 8 * r) * Dd + by + tx] = __float2half_rn(t[tx][ty + 8 * r]);
}

// single-read row softmax: values held in registers; writes fp32 + fp16
__global__ void softmax_split(float* __restrict__ W, __half* __restrict__ wh)
{
    long long row = blockIdx.x;
    float* p = W + row * (long long)Nn;
    __half* ph = wh + row * (long long)Nn;
    __shared__ float red[8];
    const int tid = threadIdx.x;
    const int lane = tid & 31, warp = tid >> 5;

    float e[8];
    {
        float4 v0 = *(const float4*)(p + tid * 8);
        float4 v1 = *(const float4*)(p + tid * 8 + 4);
        e[0]=v0.x; e[1]=v0.y; e[2]=v0.z; e[3]=v0.w;
        e[4]=v1.x; e[5]=v1.y; e[6]=v1.z; e[7]=v1.w;
    }
    float mx = e[0];
#pragma unroll
    for (int i = 1; i < 8; i++) mx = fmaxf(mx, e[i]);
#pragma unroll
    for (int s = 16; s > 0; s >>= 1)
        mx = fmaxf(mx, __shfl_xor_sync(0xffffffffu, mx, s));
    if (lane == 0) red[warp] = mx;
    __syncthreads();
    mx = red[0];
#pragma unroll
    for (int w = 1; w < 8; w++) mx = fmaxf(mx, red[w]);
    __syncthreads();

    float sum = 0.0f;
#pragma unroll
    for (int i = 0; i < 8; i++) { e[i] = expf(e[i] - mx); sum += e[i]; }
#pragma unroll
    for (int s = 16; s > 0; s >>= 1)
        sum += __shfl_xor_sync(0xffffffffu, sum, s);
    if (lane == 0) red[warp] = sum;
    __syncthreads();
    sum = red[0];
#pragma unroll
    for (int w = 1; w < 8; w++) sum += red[w];
    float inv = 1.0f / sum;

    float4 o0, o1;
    o0.x = e[0]*inv; o0.y = e[1]*inv; o0.z = e[2]*inv; o0.w = e[3]*inv;
    o1.x = e[4]*inv; o1.y = e[5]*inv; o1.z = e[6]*inv; o1.w = e[7]*inv;
    *(float4*)(p + tid * 8)     = o0;
    *(float4*)(p + tid * 8 + 4) = o1;
    *(__half2*)(ph + tid * 8)     = __floats2half2_rn(o0.x, o0.y);
    *(__half2*)(ph + tid * 8 + 2) = __floats2half2_rn(o0.z, o0.w);
    *(__half2*)(ph + tid * 8 + 4) = __floats2half2_rn(o1.x, o1.y);
    *(__half2*)(ph + tid * 8 + 6) = __floats2half2_rn(o1.z, o1.w);
}

// residual + layernorm + concat(x, ln)
__global__ void ln_concat(const float* __restrict__ x, const float* __restrict__ att,
                          const float* __restrict__ gamma, const float* __restrict__ beta,
                          float* __restrict__ out)
{
    long long row = blockIdx.x;
    const float* xr = x + row * Dd;
    const float* ar = att + row * Dd;
    float* o = out + row * (2 * Dd);
    __shared__ float red[256];
    int tid = threadIdx.x;

    float h[4], s = 0.0f;
#pragma unroll
    for (int i = 0; i < 4; i++) { int c = tid + i * 256; h[i] = xr[c] + ar[c]; s += h[i]; }
    red[tid] = s; __syncthreads();
#pragma unroll
    for (int st = 128; st > 0; st >>= 1) {
        if (tid < st) red[tid] += red[tid + st];
        __syncthreads();
    }
    float mu = red[0] * (1.0f / Dd); __syncthreads();

    float v = 0.0f;
#pragma unroll
    for (int i = 0; i < 4; i++) { float d = h[i] - mu; v += d * d; }
    red[tid] = v; __syncthreads();
#pragma unroll
    for (int st = 128; st > 0; st >>= 1) {
        if (tid < st) red[tid] += red[tid + st];
        __syncthreads();
    }
    float rstd = rsqrtf(red[0] * (1.0f / Dd) + 1e-5f);
#pragma unroll
    for (int i = 0; i < 4; i++) {
        int c = tid + i * 256;
        o[c]      = xr[c];
        o[Dd + c] = (h[i] - mu) * rstd * gamma[c] + beta[c];
    }
}

// ------------------------------- launcher -----------------------------------
extern "C" void kernel_launch(void* const* d_in, const int* in_sizes, int n_in,
                              void* d_out, int out_size)
{
    const float* x     = (const float*)d_in[0];
    const float* Wk    = (const float*)d_in[1];
    const float* bk    = (const float*)d_in[2];
    const float* Wq    = (const float*)d_in[3];
    const float* bq    = (const float*)d_in[4];
    const float* Wv    = (const float*)d_in[5];
    const float* bv    = (const float*)d_in[6];
    const float* gamma = (const float*)d_in[7];
    const float* beta  = (const float*)d_in[8];

    float* out = (float*)d_out;
    float* att = out + (long long)MT * 2 * Dd;
    float* wgt = att + (long long)MT * Dd;

    __half *x16, *W16, *QK, *Vt, *w16;
    float* bqk;
    cudaGetSymbolAddress((void**)&x16, g_x16);
    cudaGetSymbolAddress((void**)&W16, g_W16);
    cudaGetSymbolAddress((void**)&bqk, g_b);
    cudaGetSymbolAddress((void**)&QK,  g_QK);
    cudaGetSymbolAddress((void**)&Vt,  g_Vt);
    cudaGetSymbolAddress((void**)&w16, g_w16);

    cudaFuncSetAttribute(mma_gemm<0, 0>, cudaFuncAttributeMaxDynamicSharedMemorySize, SMEM_BYTES);
    cudaFuncSetAttribute(mma_gemm<1, 1>, cudaFuncAttributeMaxDynamicSharedMemorySize, SMEM_BYTES);
    cudaFuncSetAttribute(mma_gemm<1, 2>, cudaFuncAttributeMaxDynamicSharedMemorySize, SMEM_BYTES);

    // 1) precision conversions
    cvt_x<<<MT * Dd / 4096, 1024>>>(x, x16);
    copy_bias<<<2, Dd>>>(bq, bk, bqk);
    {
        dim3 g(Dd / 32, Dd / 32, 3), b(32, 8);
        transW<<<g, b>>>(Wq, Wk, Wv, W16);
    }

    // 2) fused Q,K projection: z in {Q,K}
    {
        dim3 g(Dd / BNm, MT / BMm, 2), b(256);
        mma_gemm<1, 1><<<g, b, SMEM_BYTES>>>(x16, W16, bqk, nullptr, QK,
                                             Dd, Dd,
                                             0, (long long)Dd * Dd, (long long)MT * Dd,
                                             Dd, 1.0f);
    }

    // 3) Vt[b][d,n] = Wv^T @ x_b^T + bv (bias per row) -> fp16, per batch
    {
        dim3 g(Nn / BNm, Dd / BMm, Bb), b(256);
        mma_gemm<1, 2><<<g, b, SMEM_BYTES>>>(W16 + (size_t)2 * Dd * Dd, x16, bv,
                                             nullptr, Vt,
                                             Dd, Nn,
                                             0, (long long)Nn * Dd, (long long)Dd * Nn,
                                             0, 1.0f);
    }

    // 4) scores = Q @ K^T / 32 -> wgt (fp32)
    {
        dim3 g(Nn / BNm, Nn / BMm, Bb), b(256);
        mma_gemm<0, 0><<<g, b, SMEM_BYTES>>>(QK, QK + (size_t)MT * Dd, nullptr,
                                             wgt, nullptr,
                                             Dd, Nn,
                                             (long long)Nn * Dd, (long long)Nn * Dd,
                                             (long long)Nn * Nn, 0, 1.0f / 32.0f);
    }

    // 5) softmax rows in place + fp16 copy (single gmem read)
    softmax_split<<<Bb * Nn, 256>>>(wgt, w16);

    // 6) att = weight @ V -> att (fp32)
    {
        dim3 g(Dd / BNm, Nn / BMm, Bb), b(256);
        mma_gemm<0, 0><<<g, b, SMEM_BYTES>>>(w16, Vt, nullptr, att, nullptr,
                                             Nn, Dd,
                                             (long long)Nn * Nn, (long long)Nn * Dd,
                                             (long long)Nn * Dd, 0, 1.0f);
    }

    // 7) out = concat(x, LN(x + att))
    ln_concat<<<Bb * Nn, 256>>>(x, att, gamma, beta, out);
}

// round 11
// speedup vs baseline: 1.1011x; 1.0347x over previous
#include <cuda_runtime.h>
#include <cuda_fp16.h>
#include <math.h>
#include <stdint.h>

// ---------------------------------------------------------------------------
// attention_83932250898666 : B=4, N=2048, D=1024
// d_out layout (float32):
//   [0, 16777216)        out   = concat(x, LN(x+att))   [B,N,2D]
//   [16777216, 25165824) att_score                      [B,N,D]
//   [25165824, 41943040) weight = softmax(QK^T/32)      [B,N,N]
// GEMMs: single-pass fp16 mma.sync (HMMA), fp32 accumulate.
// Round 11: strength-reduced mainloop (rotating stage ptrs, hoisted bases),
//           concat-x copy fused into cvt_x (off the critical tail).
// ---------------------------------------------------------------------------

#define Bb 4
#define Nn 2048
#define Dd 1024
#define MT (Bb*Nn)   // 8192

// ------------------------- device scratch (no allocs) ----------------------
__device__ __half g_x16[(size_t)MT * Dd];
__device__ __half g_W16[(size_t)3 * Dd * Dd];      // [z][n][k] transposed weights
__device__ float  g_b[2 * Dd];                     // biases q,k
__device__ __half g_QK[(size_t)2 * MT * Dd];       // Q | K
__device__ __half g_Vt[(size_t)MT * Dd];           // per-batch V^T [b][d][n]
__device__ __half g_w16[(size_t)Bb * Nn * Nn];     // softmax weights fp16

// ------------------------------ PTX helpers --------------------------------
__device__ __forceinline__ uint32_t smem_u32(const void* p) {
    uint32_t a;
    asm("{ .reg .u64 t; cvta.to.shared.u64 t, %1; cvt.u32.u64 %0, t; }" : "=r"(a) : "l"(p));
    return a;
}

#define CP16(dst, src) \
    asm volatile("cp.async.cg.shared.global [%0], [%1], 16;" :: "r"(dst), "l"(src))
#define CP_COMMIT() asm volatile("cp.async.commit_group;" ::: "memory")
#define CP_WAIT1()  asm volatile("cp.async.wait_group 1;" ::: "memory")

#define LDSM4(R0, R1, R2, R3, A) \
    asm volatile("ldmatrix.sync.aligned.m8n8.x4.shared.b16 {%0,%1,%2,%3}, [%4];" \
                 : "=r"(R0), "=r"(R1), "=r"(R2), "=r"(R3) : "r"(A))

#define MMAH(D, A0, A1, A2, A3, B0, B1) \
    asm volatile("mma.sync.aligned.m16n8k16.row.col.f32.f16.f16.f32 " \
                 "{%0,%1,%2,%3},{%4,%5,%6,%7},{%8,%9},{%0,%1,%2,%3};" \
                 : "+f"((D)[0]), "+f"((D)[1]), "+f"((D)[2]), "+f"((D)[3]) \
                 : "r"(A0), "r"(A1), "r"(A2), "r"(A3), "r"(B0), "r"(B1))

// ------------------------------- MMA GEMM ----------------------------------
// C[M,N] = alpha*(A @ Bmat^T)(+bias). A:[M,K] fp16 (ld=K), Bmat:[N,K] fp16 (ld=K).
// Block 128x128, 8 warps (4m x 2n), warp tile 32x64, K-chunk 64, 3-stage cp.async.
#define BMm 128
#define BNm 128
#define BKm 64
#define LDSm 72                          // padded row length in halves (144B)
#define OPA (128 * LDSm * 2)             // 18432 B
#define STGB (2 * OPA)                   // 36864 B
#define NSTAGE 3
#define SMEM_BYTES (NSTAGE * STGB)       // 110592

// EPI: 0 fp32 out, 1 fp16 out.  BIASMODE: 0 none, 1 per-col, 2 per-row.
template<int EPI, int BIASMODE>
__global__ __launch_bounds__(256, 2)
void mma_gemm(const __half* __restrict__ A, const __half* __restrict__ B,
              const float* __restrict__ bias,
              float* __restrict__ Cf, __half* __restrict__ Ch,
              int K, int ldc,
              long long sA, long long sB, long long sC, long long sBias, float alpha)
{
    extern __shared__ char smem[];
    const uint32_t sbase = smem_u32(smem);
    const int tid  = threadIdx.x;
    const int wid  = tid >> 5;
    const int lane = tid & 31;
    const int wy = wid >> 1;            // 0..3  (m, 32 rows each)
    const int wx = wid & 1;             // 0..1  (n, 64 cols each)
    const int m0 = blockIdx.y * BMm;
    const int n0 = blockIdx.x * BNm;
    A += (long long)blockIdx.z * sA;
    B += (long long)blockIdx.z * sB;
    if (BIASMODE) bias += (long long)blockIdx.z * sBias;

    float acc[2][8][4];
#pragma unroll
    for (int i = 0; i < 2; i++)
#pragma unroll
        for (int j = 0; j < 8; j++)
#pragma unroll
            for (int q = 0; q < 4; q++) acc[i][j][q] = 0.0f;

    const int nch = K / BKm;

    // hoisted per-thread gmem pointers and smem store offset for cp.async
    const int rA = tid >> 3, cA = tid & 7;
    const __half* gA = A + (long long)(m0 + rA) * K + cA * 8;  // +256/8? rows step 32
    const __half* gB = B + (long long)(n0 + rA) * K + cA * 8;
    const uint32_t soff = (uint32_t)(rA * LDSm + cA * 8) * 2;  // + t*32*LDSm*2
    const long long gstep = (long long)32 * K;                 // 32 rows

    // full-stage load (prologue only)
    auto load_stage = [&](uint32_t sb, int k0) {
#pragma unroll
        for (int t = 0; t < 4; t++)
            CP16(sb + soff + t * (32 * LDSm * 2), gA + t * gstep + k0);
#pragma unroll
        for (int t = 0; t < 4; t++)
            CP16(sb + OPA + soff + t * (32 * LDSm * 2), gB + t * gstep + k0);
    };

    // 1/8th of a stage load; p in [0,8)
    auto load_part = [&](uint32_t sb, int k0, int p) {
        if (p < 4)
            CP16(sb + soff + p * (32 * LDSm * 2), gA + p * gstep + k0);
        else
            CP16(sb + OPA + soff + (p - 4) * (32 * LDSm * 2), gB + (p - 4) * gstep + k0);
    };

    load_stage(sbase, 0);           CP_COMMIT();
    load_stage(sbase + STGB, BKm);  CP_COMMIT();

    // ldmatrix lane base addresses (smem-stage-relative)
    const int arow = (lane & 7) + ((lane >> 3) & 1) * 8;   // 0..15
    const int acol = (lane >> 4) * 8;                      // 0 / 8
    const int brow = (lane & 7) + (lane >> 4) * 8;
    const int bcol = ((lane >> 3) & 1) * 8;
    const uint32_t baseA = (uint32_t)((32 * wy + arow) * LDSm + acol) * 2;
    const uint32_t baseB = (uint32_t)((64 * wx + brow) * LDSm + bcol) * 2 + OPA;

    uint32_t af[2][2][4];      // A fragments, double buffered over ks
    uint32_t bf[2][4][2];      // B fragments, rolling buffer per half-ks (4 j each)

    auto ldA = [&](int buf, uint32_t sb, int ks) {
#pragma unroll
        for (int i = 0; i < 2; i++) {
            uint32_t aoff = sb + baseA + (uint32_t)(16 * i * LDSm + ks * 16) * 2;
            LDSM4(af[buf][i][0], af[buf][i][1], af[buf][i][2], af[buf][i][3], aoff);
        }
    };
    auto ldB = [&](int buf, uint32_t sb, int ks, int jh) {
#pragma unroll
        for (int jpp = 0; jpp < 2; jpp++) {
            uint32_t boff = sb + baseB
                          + (uint32_t)(16 * (2 * jh + jpp) * LDSm + ks * 16) * 2;
            LDSM4(bf[buf][2*jpp][0], bf[buf][2*jpp][1], bf[buf][2*jpp+1][0], bf[buf][2*jpp+1][1],
                  boff);
        }
    };

    uint32_t sb_cur = sbase;                  // stage for chunk c
    uint32_t sb_pf  = sbase + 2 * STGB;       // stage for chunk c+2
    int k_pf = 2 * BKm;                       // k0 for chunk c+2

    for (int c = 0; c < nch; c++) {
        CP_WAIT1();
        __syncthreads();
        const uint32_t sb = sb_cur;
        const bool pf = (c + 2 < nch);
        const uint32_t s2 = sb_pf;
        const int k2 = k_pf;

        ldA(0, sb, 0);
        ldB(0, sb, 0, 0);
#pragma unroll
        for (int idx = 0; idx < 8; idx++) {          // ks = idx>>1, jh = idx&1
            const int ks = idx >> 1, jh = idx & 1;
            if (idx < 7) ldB((idx + 1) & 1, sb, (idx + 1) >> 1, (idx + 1) & 1);
            if (jh == 0 && ks < 3) ldA((ks + 1) & 1, sb, ks + 1);
            if (pf) load_part(s2, k2, idx);
            const int ab = ks & 1, bb = idx & 1;
#pragma unroll
            for (int i = 0; i < 2; i++)
#pragma unroll
                for (int jj = 0; jj < 4; jj++)
                    MMAH(acc[i][jh * 4 + jj],
                         af[ab][i][0], af[ab][i][1], af[ab][i][2], af[ab][i][3],
                         bf[bb][jj][0], bf[bb][jj][1]);
        }
        CP_COMMIT();
        // rotate stage pointers (no modulo)
        sb_cur += STGB; if (sb_cur == sbase + NSTAGE * STGB) sb_cur = sbase;
        sb_pf  += STGB; if (sb_pf  == sbase + NSTAGE * STGB) sb_pf  = sbase;
        k_pf   += BKm;
    }

    // ------------------------------ epilogue --------------------------------
    const int g  = lane >> 2;
    const int t4 = lane & 3;
    const long long cb = (long long)blockIdx.z * sC;
#pragma unroll
    for (int i = 0; i < 2; i++) {
#pragma unroll
        for (int j = 0; j < 8; j++) {
            int mrow = m0 + 32 * wy + 16 * i + g;
            int ncol = n0 + 64 * wx + 8 * j + 2 * t4;
            float v00 = acc[i][j][0] * alpha, v01 = acc[i][j][1] * alpha;
            float v10 = acc[i][j][2] * alpha, v11 = acc[i][j][3] * alpha;
            long long o0 = cb + (long long)mrow * ldc + ncol;
            long long o1 = cb + (long long)(mrow + 8) * ldc + ncol;
            if (BIASMODE == 1) {
                float b0 = bias[ncol], b1 = bias[ncol + 1];
                v00 += b0; v01 += b1; v10 += b0; v11 += b1;
            } else if (BIASMODE == 2) {
                float br0 = bias[mrow], br1 = bias[mrow + 8];
                v00 += br0; v01 += br0; v10 += br1; v11 += br1;
            }
            if (EPI == 0) {
                *(float2*)(Cf + o0) = make_float2(v00, v01);
                *(float2*)(Cf + o1) = make_float2(v10, v11);
            } else {
                *(__half2*)(Ch + o0) = __floats2half2_rn(v00, v01);
                *(__half2*)(Ch + o1) = __floats2half2_rn(v10, v11);
            }
        }
    }
}

// --------------------------- aux kernels ------------------------------------
// fp32 -> fp16 AND copy x into out[:, 0:D] (concat first half, off critical path)
__global__ void cvt_x(const float* __restrict__ in, __half* __restrict__ out16,
                      float* __restrict__ outx)
{
    long long i = ((long long)blockIdx.x * blockDim.x + threadIdx.x) * 4;
    float4 v = *(const float4*)(in + i);
    *(__half2*)(out16 + i)     = __floats2half2_rn(v.x, v.y);
    *(__half2*)(out16 + i + 2) = __floats2half2_rn(v.z, v.w);
    long long row = i >> 10;              // / Dd
    long long col = i & (Dd - 1);
    *(float4*)(outx + row * (2 * Dd) + col) = v;
}

__global__ void copy_bias(const float* __restrict__ b0, const float* __restrict__ b1,
                          float* __restrict__ dst)
{
    int z = blockIdx.x;
    const float* s = (z == 0) ? b0 : b1;
    dst[z * Dd + threadIdx.x] = s[threadIdx.x];
}

// Wt[n,k] = W[k,n] fp16 ; z selects which W
__global__ void transW(const float* __restrict__ W0, const float* __restrict__ W1,
                       const float* __restrict__ W2, __half* __restrict__ out)
{
    __shared__ float t[32][33];
    const float* W = (blockIdx.z == 0) ? W0 : (blockIdx.z == 1) ? W1 : W2;
    __half* o = out + (size_t)blockIdx.z * Dd * Dd;
    int bx = blockIdx.x * 32, by = blockIdx.y * 32;
    int tx = threadIdx.x, ty = threadIdx.y;
#pragma unroll
    for (int r = 0; r < 4; r++)
        t[ty + 8 * r][tx] = W[(long long)(by + ty + 8 * r) * Dd + bx + tx];
    __syncthreads();
#pragma unroll
    for (int r = 0; r < 4; r++)
        o[(long long)(bx + ty + 8 * r) * Dd + by + tx] = __float2half_rn(t[tx][ty + 8 * r]);
}

// single-read row softmax: values held in registers; writes fp32 + fp16
__global__ void softmax_split(float* __restrict__ W, __half* __restrict__ wh)
{
    long long row = blockIdx.x;
    float* p = W + row * (long long)Nn;
    __half* ph = wh + row * (long long)Nn;
    __shared__ float red[8];
    const int tid = threadIdx.x;
    const int lane = tid & 31, warp = tid >> 5;

    float e[8];
    {
        float4 v0 = *(const float4*)(p + tid * 8);
        float4 v1 = *(const float4*)(p + tid * 8 + 4);
        e[0]=v0.x; e[1]=v0.y; e[2]=v0.z; e[3]=v0.w;
        e[4]=v1.x; e[5]=v1.y; e[6]=v1.z; e[7]=v1.w;
    }
    float mx = e[0];
#pragma unroll
    for (int i = 1; i < 8; i++) mx = fmaxf(mx, e[i]);
#pragma unroll
    for (int s = 16; s > 0; s >>= 1)
        mx = fmaxf(mx, __shfl_xor_sync(0xffffffffu, mx, s));
    if (lane == 0) red[warp] = mx;
    __syncthreads();
    mx = red[0];
#pragma unroll
    for (int w = 1; w < 8; w++) mx = fmaxf(mx, red[w]);
    __syncthreads();

    float sum = 0.0f;
#pragma unroll
    for (int i = 0; i < 8; i++) { e[i] = expf(e[i] - mx); sum += e[i]; }
#pragma unroll
    for (int s = 16; s > 0; s >>= 1)
        sum += __shfl_xor_sync(0xffffffffu, sum, s);
    if (lane == 0) red[warp] = sum;
    __syncthreads();
    sum = red[0];
#pragma unroll
    for (int w = 1; w < 8; w++) sum += red[w];
    float inv = 1.0f / sum;

    float4 o0, o1;
    o0.x = e[0]*inv; o0.y = e[1]*inv; o0.z = e[2]*inv; o0.w = e[3]*inv;
    o1.x = e[4]*inv; o1.y = e[5]*inv; o1.z = e[6]*inv; o1.w = e[7]*inv;
    *(float4*)(p + tid * 8)     = o0;
    *(float4*)(p + tid * 8 + 4) = o1;
    *(__half2*)(ph + tid * 8)     = __floats2half2_rn(o0.x, o0.y);
    *(__half2*)(ph + tid * 8 + 2) = __floats2half2_rn(o0.z, o0.w);
    *(__half2*)(ph + tid * 8 + 4) = __floats2half2_rn(o1.x, o1.y);
    *(__half2*)(ph + tid * 8 + 6) = __floats2half2_rn(o1.z, o1.w);
}

// residual + layernorm; writes only out[:, D:2D] (x half written by cvt_x)
__global__ void ln_concat(const float* __restrict__ x, const float* __restrict__ att,
                          const float* __restrict__ gamma, const float* __restrict__ beta,
                          float* __restrict__ out)
{
    long long row = blockIdx.x;
    const float* xr = x + row * Dd;
    const float* ar = att + row * Dd;
    float* o = out + row * (2 * Dd);
    __shared__ float red[256];
    int tid = threadIdx.x;

    float h[4], s = 0.0f;
#pragma unroll
    for (int i = 0; i < 4; i++) { int c = tid + i * 256; h[i] = xr[c] + ar[c]; s += h[i]; }
    red[tid] = s; __syncthreads();
#pragma unroll
    for (int st = 128; st > 0; st >>= 1) {
        if (tid < st) red[tid] += red[tid + st];
        __syncthreads();
    }
    float mu = red[0] * (1.0f / Dd); __syncthreads();

    float v = 0.0f;
#pragma unroll
    for (int i = 0; i < 4; i++) { float d = h[i] - mu; v += d * d; }
    red[tid] = v; __syncthreads();
#pragma unroll
    for (int st = 128; st > 0; st >>= 1) {
        if (tid < st) red[tid] += red[tid + st];
        __syncthreads();
    }
    float rstd = rsqrtf(red[0] * (1.0f / Dd) + 1e-5f);
#pragma unroll
    for (int i = 0; i < 4; i++) {
        int c = tid + i * 256;
        o[Dd + c] = (h[i] - mu) * rstd * gamma[c] + beta[c];
    }
}

// ------------------------------- launcher -----------------------------------
extern "C" void kernel_launch(void* const* d_in, const int* in_sizes, int n_in,
                              void* d_out, int out_size)
{
    const float* x     = (const float*)d_in[0];
    const float* Wk    = (const float*)d_in[1];
    const float* bk    = (const float*)d_in[2];
    const float* Wq    = (const float*)d_in[3];
    const float* bq    = (const float*)d_in[4];
    const float* Wv    = (const float*)d_in[5];
    const float* bv    = (const float*)d_in[6];
    const float* gamma = (const float*)d_in[7];
    const float* beta  = (const float*)d_in[8];

    float* out = (float*)d_out;
    float* att = out + (long long)MT * 2 * Dd;
    float* wgt = att + (long long)MT * Dd;

    __half *x16, *W16, *QK, *Vt, *w16;
    float* bqk;
    cudaGetSymbolAddress((void**)&x16, g_x16);
    cudaGetSymbolAddress((void**)&W16, g_W16);
    cudaGetSymbolAddress((void**)&bqk, g_b);
    cudaGetSymbolAddress((void**)&QK,  g_QK);
    cudaGetSymbolAddress((void**)&Vt,  g_Vt);
    cudaGetSymbolAddress((void**)&w16, g_w16);

    cudaFuncSetAttribute(mma_gemm<0, 0>, cudaFuncAttributeMaxDynamicSharedMemorySize, SMEM_BYTES);
    cudaFuncSetAttribute(mma_gemm<1, 1>, cudaFuncAttributeMaxDynamicSharedMemorySize, SMEM_BYTES);
    cudaFuncSetAttribute(mma_gemm<1, 2>, cudaFuncAttributeMaxDynamicSharedMemorySize, SMEM_BYTES);

    // 1) precision conversions (+ concat x half)
    cvt_x<<<MT * Dd / 4096, 1024>>>(x, x16, out);
    copy_bias<<<2, Dd>>>(bq, bk, bqk);
    {
        dim3 g(Dd / 32, Dd / 32, 3), b(32, 8);
        transW<<<g, b>>>(Wq, Wk, Wv, W16);
    }

    // 2) fused Q,K projection: z in {Q,K}
    {
        dim3 g(Dd / BNm, MT / BMm, 2), b(256);
        mma_gemm<1, 1><<<g, b, SMEM_BYTES>>>(x16, W16, bqk, nullptr, QK,
                                             Dd, Dd,
                                             0, (long long)Dd * Dd, (long long)MT * Dd,
                                             Dd, 1.0f);
    }

    // 3) Vt[b][d,n] = Wv^T @ x_b^T + bv (bias per row) -> fp16, per batch
    {
        dim3 g(Nn / BNm, Dd / BMm, Bb), b(256);
        mma_gemm<1, 2><<<g, b, SMEM_BYTES>>>(W16 + (size_t)2 * Dd * Dd, x16, bv,
                                             nullptr, Vt,
                                             Dd, Nn,
                                             0, (long long)Nn * Dd, (long long)Dd * Nn,
                                             0, 1.0f);
    }

    // 4) scores = Q @ K^T / 32 -> wgt (fp32)
    {
        dim3 g(Nn / BNm, Nn / BMm, Bb), b(256);
        mma_gemm<0, 0><<<g, b, SMEM_BYTES>>>(QK, QK + (size_t)MT * Dd, nullptr,
                                             wgt, nullptr,
                                             Dd, Nn,
                                             (long long)Nn * Dd, (long long)Nn * Dd,
                                             (long long)Nn * Nn, 0, 1.0f / 32.0f);
    }

    // 5) softmax rows in place + fp16 copy (single gmem read)
    softmax_split<<<Bb * Nn, 256>>>(wgt, w16);

    // 6) att = weight @ V -> att (fp32)
    {
        dim3 g(Dd / BNm, Nn / BMm, Bb), b(256);
        mma_gemm<0, 0><<<g, b, SMEM_BYTES>>>(w16, Vt, nullptr, att, nullptr,
                                             Nn, Dd,
                                             (long long)Nn * Nn, (long long)Nn * Dd,
                                             (long long)Nn * Dd, 0, 1.0f);
    }

    // 7) out[:, D:2D] = LN(x + att)
    ln_concat<<<Bb * Nn, 256>>>(x, att, gamma, beta, out);
}